// round 8
// baseline (speedup 1.0000x reference)
#include <cuda_runtime.h>
#include <cstdint>

// Problem constants
#define BNUM 4
#define SEQ  1024
#define EMBD 1024
#define NH   16
#define HD   64
#define BH   (BNUM * NH)
#define ATT_SCALE (1.0f / 32.0f)   // 1/sqrt(1024), applied to (logits+mask)
#define NEG_INF __int_as_float(0xff800000)

// Scratch (allocation-free contract: __device__ globals)
__device__ float g_q[BH * SEQ * HD];          // [bh][s][d], tf32-rounded
__device__ float g_k[BH * SEQ * HD];          // [bh][s][d], tf32-rounded
__device__ float g_vT[BH * HD * SEQ];         // [bh][d][s], tf32-rounded
__device__ float g_ctx[BNUM * SEQ * EMBD];    // tf32-rounded (attn epilogue)
__device__ float g_xr[3 * BNUM * SEQ * EMBD]; // tf32-rounded inputs k/v/q
// Transposed (B = [N,K] K-major) weights, pre-rounded to tf32
__device__ float g_wT[3 * EMBD * EMBD];       // k/v/q
__device__ float g_woT[EMBD * EMBD];

__device__ __forceinline__ float to_tf32(float x) {
    float y; asm("cvt.rna.tf32.f32 %0, %1;" : "=f"(y) : "f"(x)); return y;
}
__device__ __forceinline__ uint32_t smem_u32(const void* p) {
    uint32_t a;
    asm("{ .reg .u64 t; cvta.to.shared.u64 t, %1; cvt.u32.u64 %0, t; }"
        : "=r"(a) : "l"(p));
    return a;
}

__device__ __forceinline__ void mma_m16n8k8(float (&d)[4], const uint32_t (&a)[4],
                                            const uint32_t b0, const uint32_t b1) {
    asm volatile(
        "mma.sync.aligned.m16n8k8.row.col.f32.tf32.tf32.f32 "
        "{%0,%1,%2,%3}, {%4,%5,%6,%7}, {%8,%9}, {%0,%1,%2,%3};"
        : "+f"(d[0]), "+f"(d[1]), "+f"(d[2]), "+f"(d[3])
        : "r"(a[0]), "r"(a[1]), "r"(a[2]), "r"(a[3]), "r"(b0), "r"(b1));
}

#define LDMX4(r, addr) \
    asm volatile("ldmatrix.sync.aligned.m8n8.x4.shared.b16 {%0,%1,%2,%3}, [%4];" \
        : "=r"((r)[0]), "=r"((r)[1]), "=r"((r)[2]), "=r"((r)[3]) : "r"(addr))

#define CP16(dst, src) \
    asm volatile("cp.async.cg.shared.global [%0], [%1], 16;" :: "r"(dst), "l"(src))
#define CP_COMMIT() asm volatile("cp.async.commit_group;" ::: "memory")
template<int N> __device__ __forceinline__ void cp_wait() {
    asm volatile("cp.async.wait_group %0;" :: "n"(N) : "memory");
}

// ---------------------------------------------------------------------------
// tf32 tensor-core GEMM v2: C[128x256] = A[M,K] @ Bt[N,K]^T, K=1024, BK=32.
// 8 warps, warp tile 64x64 (4x8 m16n8k8) -> halves smem fragment traffic per
// MMA vs the old 64x32 tile (GEMM was smem-crossbar co-limited).
// 3-stage cp.async pipeline; ldmatrix tf32 fragments; 1 CTA/SM (~200 regs).
// smem per stage: A 128x32f (16KB) + B 256x32f (32KB); row-chunk XOR swizzle.
// ---------------------------------------------------------------------------
#define A_BYTES 16384                   // 128 rows * 8 chunks * 16B
#define B_BYTES 32768                   // 256 rows * 8 chunks * 16B
#define STG_BYTES (A_BYTES + B_BYTES)   // 48KB
#define GEMM_SMEM (3 * STG_BYTES)       // 144KB

__device__ __forceinline__ void gemm_tf32(const float* __restrict__ A,
                                          const float* __restrict__ Bt,
                                          char* sm, float (&c)[4][8][4])
{
    const int tid  = threadIdx.x;
    const int lane = tid & 31;
    const int warp = tid >> 5;
    const int m0   = blockIdx.x * 128;
    const int n0   = blockIdx.y * 256;
    const uint32_t sb = smem_u32(sm);

    auto issue = [&](int stage, int k0) {
        const uint32_t sa  = sb + stage * STG_BYTES;
        const uint32_t sbb = sa + A_BYTES;
        #pragma unroll
        for (int i = 0; i < 4; i++) {          // A: 1024 CP16
            const int idx = i * 256 + tid;
            const int row = idx >> 3, ch = idx & 7;
            const uint32_t off = (uint32_t)((row << 3) + (ch ^ (row & 7))) << 4;
            CP16(sa + off, A + (size_t)(m0 + row) * EMBD + k0 + ch * 4);
        }
        #pragma unroll
        for (int i = 0; i < 8; i++) {          // B: 2048 CP16
            const int idx = i * 256 + tid;
            const int row = idx >> 3, ch = idx & 7;
            const uint32_t off = (uint32_t)((row << 3) + (ch ^ (row & 7))) << 4;
            CP16(sbb + off, Bt + (size_t)(n0 + row) * EMBD + k0 + ch * 4);
        }
        CP_COMMIT();
    };

    issue(0, 0);
    issue(1, 32);

    const int l7   = lane & 7;
    const int wm   = (warp & 1) * 64;
    const int wn   = (warp >> 1) * 64;
    const int aRow = wm + l7 + ((lane >> 3) & 1) * 8;  // + mi*16
    const int aChO = lane >> 4;                        // 0/1 (k lo/hi half)
    const int bRow = wn + l7 + (lane >> 4) * 8;        // + p*16
    const int bChO = (lane >> 3) & 1;

    for (int ch = 0; ch < 32; ch++) {
        const int st = ch % 3;
        if (ch < 30) cp_wait<1>(); else cp_wait<0>();
        __syncthreads();
        if (ch + 2 < 32) issue((ch + 2) % 3, (ch + 2) * 32);

        const uint32_t sa  = sb + st * STG_BYTES;
        const uint32_t sbb = sa + A_BYTES;

        #pragma unroll
        for (int ks = 0; ks < 4; ks++) {
            uint32_t af[4][4], bq[4][4];
            #pragma unroll
            for (int mi = 0; mi < 4; mi++) {
                const int row = aRow + mi * 16;
                const uint32_t addr =
                    sa + ((uint32_t)((row << 3) + ((ks * 2 + aChO) ^ (row & 7))) << 4);
                LDMX4(af[mi], addr);
            }
            #pragma unroll
            for (int p = 0; p < 4; p++) {
                const int row = bRow + p * 16;
                const uint32_t addr =
                    sbb + ((uint32_t)((row << 3) + ((ks * 2 + bChO) ^ (row & 7))) << 4);
                LDMX4(bq[p], addr);
            }
            #pragma unroll
            for (int mi = 0; mi < 4; mi++)
                #pragma unroll
                for (int ni = 0; ni < 8; ni++)
                    mma_m16n8k8(c[mi][ni], af[mi],
                                bq[ni >> 1][(ni & 1) * 2],
                                bq[ni >> 1][(ni & 1) * 2 + 1]);
        }
    }
}

// Projection: outputs tf32-rounded Q/K (as [bh][s][d]) and V transposed [bh][d][s]
__global__ __launch_bounds__(256, 1) void proj_tc()
{
    extern __shared__ char smc[];
    const int z = blockIdx.z;
    const float* A  = g_xr + (size_t)z * BNUM * SEQ * EMBD;
    const float* Bt = g_wT + (size_t)z * EMBD * EMBD;

    float c[4][8][4] = {};
    gemm_tf32(A, Bt, smc, c);

    const int tid = threadIdx.x;
    const int lane = tid & 31, warp = tid >> 5;
    const int wm = (warp & 1) * 64, wn = (warp >> 1) * 64;
    const int g = lane >> 2, tg = lane & 3;
    const int m0 = blockIdx.x * 128, n0 = blockIdx.y * 256;

    if (z == 1) {
        // V -> g_vT [bh][d][s]
        #pragma unroll
        for (int mi = 0; mi < 4; mi++) {
            #pragma unroll
            for (int ni = 0; ni < 8; ni++) {
                const int n = n0 + wn + ni * 8 + tg * 2;
                const int h = n >> 6, d = n & 63;
                #pragma unroll
                for (int half = 0; half < 2; half++) {
                    const int m = m0 + wm + mi * 16 + g + half * 8;
                    const int b = m >> 10, s = m & 1023;
                    const size_t base = (size_t)(b * NH + h) * HD;
                    g_vT[(base + d)     * SEQ + s] = to_tf32(c[mi][ni][half * 2]);
                    g_vT[(base + d + 1) * SEQ + s] = to_tf32(c[mi][ni][half * 2 + 1]);
                }
            }
        }
    } else {
        float* Out = (z == 0) ? g_k : g_q;
        #pragma unroll
        for (int mi = 0; mi < 4; mi++) {
            #pragma unroll
            for (int ni = 0; ni < 8; ni++) {
                const int n = n0 + wn + ni * 8 + tg * 2;
                const int h = n >> 6, d = n & 63;
                #pragma unroll
                for (int half = 0; half < 2; half++) {
                    const int m = m0 + wm + mi * 16 + g + half * 8;
                    const int b = m >> 10, s = m & 1023;
                    float2 v = make_float2(to_tf32(c[mi][ni][half * 2]),
                                           to_tf32(c[mi][ni][half * 2 + 1]));
                    *(float2*)&Out[((size_t)(b * NH + h) * SEQ + s) * HD + d] = v;
                }
            }
        }
    }
}

// Output projection: A = g_ctx (tf32-rounded), Bt = g_woT, bias + relu
__global__ __launch_bounds__(256, 1) void outproj_tc(const float* __restrict__ bo,
                                                     float* __restrict__ out)
{
    extern __shared__ char smc[];
    float c[4][8][4] = {};
    gemm_tf32(g_ctx, g_woT, smc, c);

    const int tid = threadIdx.x;
    const int lane = tid & 31, warp = tid >> 5;
    const int wm = (warp & 1) * 64, wn = (warp >> 1) * 64;
    const int g = lane >> 2, tg = lane & 3;
    const int m0 = blockIdx.x * 128, n0 = blockIdx.y * 256;

    #pragma unroll
    for (int mi = 0; mi < 4; mi++) {
        #pragma unroll
        for (int ni = 0; ni < 8; ni++) {
            const int n = n0 + wn + ni * 8 + tg * 2;
            const float b0 = bo[n], b1 = bo[n + 1];
            #pragma unroll
            for (int half = 0; half < 2; half++) {
                const int m = m0 + wm + mi * 16 + g + half * 8;
                float2 v = make_float2(fmaxf(c[mi][ni][half * 2]     + b0, 0.0f),
                                       fmaxf(c[mi][ni][half * 2 + 1] + b1, 0.0f));
                *(float2*)&out[(size_t)m * EMBD + n] = v;
            }
        }
    }
}

// ---------------------------------------------------------------------------
// Input pre-rounding to tf32 (cp.async path cannot convert in-flight)
// ---------------------------------------------------------------------------
__global__ __launch_bounds__(256) void round_inputs(const float* __restrict__ Xk,
                                                    const float* __restrict__ Xv,
                                                    const float* __restrict__ Xq)
{
    const int z = blockIdx.y;
    const float* X = (z == 0) ? Xk : (z == 1) ? Xv : Xq;
    float* D = g_xr + (size_t)z * BNUM * SEQ * EMBD;
    const int i = blockIdx.x * 256 + threadIdx.x;   // float4 index, 1M per tensor
    float4 v = *(const float4*)(X + (size_t)i * 4);
    v.x = to_tf32(v.x); v.y = to_tf32(v.y); v.z = to_tf32(v.z); v.w = to_tf32(v.w);
    *(float4*)(D + (size_t)i * 4) = v;
}

// ---------------------------------------------------------------------------
// Weight transposes (once per launch), baking in tf32 rounding.
// ---------------------------------------------------------------------------
__global__ __launch_bounds__(256) void transpose_w(const float* __restrict__ Wk,
                                                   const float* __restrict__ Wv,
                                                   const float* __restrict__ Wq)
{
    __shared__ float sm[32][65];
    const int z = blockIdx.z;
    const float* W = (z == 0) ? Wk : (z == 1) ? Wv : Wq;
    float* WT = g_wT + (size_t)z * EMBD * EMBD;
    const int h = blockIdx.x;
    const int k0 = blockIdx.y * 32;
    const int tid = threadIdx.x;

    for (int idx = tid; idx < 32 * 64; idx += 256) {
        const int r = idx >> 6, d = idx & 63;
        sm[r][d] = to_tf32(W[((size_t)h * EMBD + (k0 + r)) * HD + d]);
    }
    __syncthreads();
    for (int idx = tid; idx < 64 * 32; idx += 256) {
        const int dd = idx >> 5, kk = idx & 31;
        WT[(size_t)(h * HD + dd) * EMBD + k0 + kk] = sm[kk][dd];
    }
}

__global__ __launch_bounds__(256) void transpose_wo(const float* __restrict__ Wo)
{
    __shared__ float sm[32][33];
    const int n0 = blockIdx.x * 32;
    const int k0 = blockIdx.y * 32;
    const int tid = threadIdx.x;

    for (int idx = tid; idx < 1024; idx += 256) {
        const int r = idx >> 5, c = idx & 31;
        sm[r][c] = to_tf32(Wo[(size_t)(k0 + r) * EMBD + n0 + c]);
    }
    __syncthreads();
    for (int idx = tid; idx < 1024; idx += 256) {
        const int rr = idx >> 5, cc = idx & 31;
        g_woT[(size_t)(n0 + rr) * EMBD + k0 + cc] = sm[cc][rr];
    }
}

// ---------------------------------------------------------------------------
// Tensor-core flash attention (unchanged from R7):
// cp.async double-buffered K/V^T tiles, ldmatrix fragments.
// ---------------------------------------------------------------------------
#define KP 68
#define ATT_TILE 16384
#define ATTN_SMEM (4 * ATT_TILE + 8 * 16 * KP * (int)sizeof(float))

__device__ __forceinline__ uint32_t att_off(int row, int ch) {
    return (uint32_t)((row << 4) + ((ch & 8) | ((ch ^ row) & 7))) << 4;
}

__global__ __launch_bounds__(256, 1) void attn_tc()
{
    extern __shared__ char smc[];
    const uint32_t sb = smem_u32(smc);
    float* Ps = (float*)(smc + 4 * ATT_TILE);   // [8 warps][16 q][KP keys]

    const int bh = blockIdx.x;
    const int qt = 7 - blockIdx.y;        // heavy tiles first
    const int q0 = qt * 128;
    const int tid = threadIdx.x, lane = tid & 31, warp = tid >> 5;
    const int g = lane >> 2, tg = lane & 3;
    const int l7 = lane & 7;
    const int fRowO = l7 + (lane >> 4) * 8;      // B-fragment row offset
    const int fChO  = (lane >> 3) & 1;           // B-fragment chunk offset
    const int wq = q0 + warp * 16;

    const float* Qg = g_q  + (size_t)bh * SEQ * HD;
    const float* Kg = g_k  + (size_t)bh * SEQ * HD;
    const float* Vg = g_vT + (size_t)bh * HD * SEQ;
    float* Pw = Ps + warp * 16 * KP;

    auto issueKV = [&](int kt) {
        const int k0 = kt * 64;
        const uint32_t kb = sb + (kt & 1) * ATT_TILE;
        const uint32_t vb = sb + 2 * ATT_TILE + (kt & 1) * ATT_TILE;
        #pragma unroll
        for (int i = 0; i < 4; i++) {
            const int idx = i * 256 + tid;
            const int row = idx >> 4, ch = idx & 15;
            const uint32_t o = att_off(row, ch);
            CP16(kb + o, Kg + (size_t)(k0 + row) * HD + ch * 4);
            CP16(vb + o, Vg + (size_t)row * SEQ + k0 + ch * 4);
        }
        CP_COMMIT();
    };

    // Q fragments for the whole block (16 x 64, 8 k-steps)
    uint32_t aq[8][4];
    #pragma unroll
    for (int kk = 0; kk < 8; kk++) {
        aq[kk][0] = __float_as_uint(Qg[(size_t)(wq + g)     * HD + kk * 8 + tg]);
        aq[kk][1] = __float_as_uint(Qg[(size_t)(wq + g + 8) * HD + kk * 8 + tg]);
        aq[kk][2] = __float_as_uint(Qg[(size_t)(wq + g)     * HD + kk * 8 + tg + 4]);
        aq[kk][3] = __float_as_uint(Qg[(size_t)(wq + g + 8) * HD + kk * 8 + tg + 4]);
    }

    float o[8][4] = {};
    float m_r[2] = { NEG_INF, NEG_INF };
    float l_r[2] = { 0.0f, 0.0f };

    const int ktend = 2 * qt + 2;
    issueKV(0);

    for (int kt = 0; kt < ktend; kt++) {
        const int k0 = kt * 64;
        cp_wait<0>();
        __syncthreads();
        if (kt + 1 < ktend) issueKV(kt + 1);

        const uint32_t kb = sb + (kt & 1) * ATT_TILE;
        const uint32_t vb = sb + 2 * ATT_TILE + (kt & 1) * ATT_TILE;

        // S = Q K^T   (B fragments via ldmatrix)
        float cs[8][4] = {};
        #pragma unroll
        for (int kk = 0; kk < 8; kk++) {
            const int ch = 2 * kk + fChO;
            #pragma unroll
            for (int n16 = 0; n16 < 4; n16++) {
                uint32_t bk[4];
                LDMX4(bk, kb + att_off(n16 * 16 + fRowO, ch));
                mma_m16n8k8(cs[2 * n16],     aq[kk], bk[0], bk[1]);
                mma_m16n8k8(cs[2 * n16 + 1], aq[kk], bk[2], bk[3]);
            }
        }

        // scale + causal mask (only last two key tiles can cross the diagonal)
        const bool msk = (kt >= 2 * qt);
        #pragma unroll
        for (int ni = 0; ni < 8; ni++) {
            #pragma unroll
            for (int e = 0; e < 4; e++) {
                float s = cs[ni][e] * ATT_SCALE;
                if (msk) {
                    const int q = wq + g + ((e >> 1) << 3);
                    const int k = k0 + ni * 8 + tg * 2 + (e & 1);
                    if (k > q) s = NEG_INF;
                }
                cs[ni][e] = s;
            }
        }

        // online softmax (rows g and g+8), quad reductions
        #pragma unroll
        for (int hh = 0; hh < 2; hh++) {
            float mx = NEG_INF;
            #pragma unroll
            for (int ni = 0; ni < 8; ni++)
                mx = fmaxf(mx, fmaxf(cs[ni][2 * hh], cs[ni][2 * hh + 1]));
            mx = fmaxf(mx, __shfl_xor_sync(0xffffffff, mx, 1));
            mx = fmaxf(mx, __shfl_xor_sync(0xffffffff, mx, 2));
            const float mnew = fmaxf(m_r[hh], mx);
            const float alpha = __expf(m_r[hh] - mnew);
            float sum = 0.0f;
            #pragma unroll
            for (int ni = 0; ni < 8; ni++) {
                const float p0 = __expf(cs[ni][2 * hh]     - mnew);
                const float p1 = __expf(cs[ni][2 * hh + 1] - mnew);
                cs[ni][2 * hh] = p0; cs[ni][2 * hh + 1] = p1;
                sum += p0 + p1;
            }
            sum += __shfl_xor_sync(0xffffffff, sum, 1);
            sum += __shfl_xor_sync(0xffffffff, sum, 2);
            l_r[hh] = l_r[hh] * alpha + sum;
            m_r[hh] = mnew;
            #pragma unroll
            for (int ni = 0; ni < 8; ni++) {
                o[ni][2 * hh] *= alpha; o[ni][2 * hh + 1] *= alpha;
            }
        }

        // P -> warp-private SMEM (tf32)
        #pragma unroll
        for (int ni = 0; ni < 8; ni++) {
            Pw[g * KP + ni * 8 + tg * 2]           = to_tf32(cs[ni][0]);
            Pw[g * KP + ni * 8 + tg * 2 + 1]       = to_tf32(cs[ni][1]);
            Pw[(g + 8) * KP + ni * 8 + tg * 2]     = to_tf32(cs[ni][2]);
            Pw[(g + 8) * KP + ni * 8 + tg * 2 + 1] = to_tf32(cs[ni][3]);
        }
        __syncwarp();

        // O += P V   (B = V^T fragments via ldmatrix)
        #pragma unroll
        for (int kk = 0; kk < 8; kk++) {
            uint32_t ap[4];
            ap[0] = __float_as_uint(Pw[g * KP + kk * 8 + tg]);
            ap[1] = __float_as_uint(Pw[(g + 8) * KP + kk * 8 + tg]);
            ap[2] = __float_as_uint(Pw[g * KP + kk * 8 + tg + 4]);
            ap[3] = __float_as_uint(Pw[(g + 8) * KP + kk * 8 + tg + 4]);
            const int ch = 2 * kk + fChO;
            #pragma unroll
            for (int n16 = 0; n16 < 4; n16++) {
                uint32_t bv[4];
                LDMX4(bv, vb + att_off(n16 * 16 + fRowO, ch));
                mma_m16n8k8(o[2 * n16],     ap, bv[0], bv[1]);
                mma_m16n8k8(o[2 * n16 + 1], ap, bv[2], bv[3]);
            }
        }
    }

    // epilogue: normalize and write concat ctx (tf32-rounded for outproj)
    const int b = bh >> 4;
    const int h4 = bh & 15;
    const float inv0 = 1.0f / l_r[0];
    const float inv1 = 1.0f / l_r[1];
    #pragma unroll
    for (int ni = 0; ni < 8; ni++) {
        const int d = h4 * 64 + ni * 8 + tg * 2;
        const int r0 = wq + g, r1 = wq + g + 8;
        *(float2*)&g_ctx[(size_t)(b * SEQ + r0) * EMBD + d] =
            make_float2(to_tf32(o[ni][0] * inv0), to_tf32(o[ni][1] * inv0));
        *(float2*)&g_ctx[(size_t)(b * SEQ + r1) * EMBD + d] =
            make_float2(to_tf32(o[ni][2] * inv1), to_tf32(o[ni][3] * inv1));
    }
}

// ---------------------------------------------------------------------------
extern "C" void kernel_launch(void* const* d_in, const int* in_sizes, int n_in,
                              void* d_out, int out_size)
{
    const float* Xk = (const float*)d_in[0];
    const float* Xv = (const float*)d_in[1];
    const float* Xq = (const float*)d_in[2];
    const float* Wk = (const float*)d_in[3];
    const float* Wv = (const float*)d_in[4];
    const float* Wq = (const float*)d_in[5];
    const float* Wo = (const float*)d_in[6];
    const float* bo = (const float*)d_in[7];
    float* out = (float*)d_out;

    cudaFuncSetAttribute(proj_tc, cudaFuncAttributeMaxDynamicSharedMemorySize, GEMM_SMEM);
    cudaFuncSetAttribute(outproj_tc, cudaFuncAttributeMaxDynamicSharedMemorySize, GEMM_SMEM);
    cudaFuncSetAttribute(attn_tc, cudaFuncAttributeMaxDynamicSharedMemorySize, ATTN_SMEM);

    // 0) pre-round inputs + transpose weights to [N,K] K-major (tf32)
    round_inputs<<<dim3(4096, 3), 256>>>(Xk, Xv, Xq);
    transpose_w<<<dim3(NH, 32, 3), 256>>>(Wk, Wv, Wq);
    transpose_wo<<<dim3(32, 32), 256>>>(Wo);
    // 1) QKV projections (128x256 CTA tile, 64x64 warp tile)
    proj_tc<<<dim3(32, 4, 3), 256, GEMM_SMEM>>>();
    // 2) causal flash attention (cp.async double-buffered, ldmatrix frags)
    attn_tc<<<dim3(BH, 8), 256, ATTN_SMEM>>>();
    // 3) output projection + bias + relu
    outproj_tc<<<dim3(32, 4), 256, GEMM_SMEM>>>(bo, out);
}